// round 1
// baseline (speedup 1.0000x reference)
#include <cuda_runtime.h>

#define BB 64
#define TT 512
#define DD 768
#define VV 20
#define NEGC (-1000000000.0f)

// Scratch (no device allocation allowed)
__device__ float g_msum[BB * DD];     // masked token sum per (b,d)
__device__ float g_scores[BB * TT];   // raw pooling scores

// ---------------------------------------------------------------------------
// K0: zero masked-sum scratch and the pooled-embedding output region
// ---------------------------------------------------------------------------
__global__ void k0_zero(float* __restrict__ out_pooled) {
    int i = blockIdx.x * blockDim.x + threadIdx.x;
    if (i < BB * DD) {
        g_msum[i] = 0.0f;
        out_pooled[i] = 0.0f;
    }
}

// ---------------------------------------------------------------------------
// K1: masked_sum[b,d] = sum_t mask[b,t] * emb[b,t,d]
// grid (8 t-chunks, 64 b), block = 768 threads (one per d). Coalesced rows.
// ---------------------------------------------------------------------------
__global__ void k1_msum(const float* __restrict__ emb,
                        const int* __restrict__ emask) {
    int b = blockIdx.y;
    int t0 = blockIdx.x * 64;
    int d = threadIdx.x;
    __shared__ float sm[64];
    if (threadIdx.x < 64)
        sm[threadIdx.x] = (float)emask[b * TT + t0 + threadIdx.x];
    __syncthreads();

    const float* e = emb + ((size_t)(b * TT + t0)) * DD + d;
    float acc = 0.0f;
#pragma unroll 8
    for (int i = 0; i < 64; i++)
        acc += sm[i] * e[(size_t)i * DD];
    atomicAdd(&g_msum[b * DD + d], acc);
}

// ---------------------------------------------------------------------------
// K2: value scores -> softmax over V=20 -> value_probs, value_embedding
// grid 64 (one block per b), block = 640 (20 warps, one per v)
// ---------------------------------------------------------------------------
__global__ void k2_value(const float* __restrict__ W,
                         const int* __restrict__ vmask,
                         float* __restrict__ out_ve,
                         float* __restrict__ out_vp) {
    int b = blockIdx.x;
    int tid = threadIdx.x;
    int warp = tid >> 5;
    int lane = tid & 31;
    __shared__ float s_sc[VV];
    __shared__ float s_p[VV];

    if (warp < VV) {
        const float* ms = g_msum + b * DD;
        const float* w = W + warp * DD;
        float acc = 0.0f;
        for (int d = lane; d < DD; d += 32)
            acc += ms[d] * w[d];
#pragma unroll
        for (int o = 16; o; o >>= 1)
            acc += __shfl_xor_sync(0xffffffffu, acc, o);
        if (lane == 0)
            s_sc[warp] = acc + (1.0f - (float)vmask[b * VV + warp]) * NEGC;
    }
    __syncthreads();

    if (tid < 32) {
        float v = (tid < VV) ? s_sc[tid] : -3.4e38f;
        float mx = v;
#pragma unroll
        for (int o = 16; o; o >>= 1)
            mx = fmaxf(mx, __shfl_xor_sync(0xffffffffu, mx, o));
        float ev = (tid < VV) ? expf(v - mx) : 0.0f;
        float s = ev;
#pragma unroll
        for (int o = 16; o; o >>= 1)
            s += __shfl_xor_sync(0xffffffffu, s, o);
        float p = ev / s;
        if (tid < VV) {
            s_p[tid] = p;
            out_vp[b * VV + tid] = p;
        }
    }
    __syncthreads();

    // value_embedding[b,d] = sum_v p[v] * W[v,d]
    for (int d = tid; d < DD; d += blockDim.x) {
        float acc = 0.0f;
#pragma unroll
        for (int v = 0; v < VV; v++)
            acc += s_p[v] * W[v * DD + d];
        out_ve[b * DD + d] = acc;
    }
}

// ---------------------------------------------------------------------------
// K3a: pooling_scores[b,t] = <emb[b,t,:], ve[b,:]> + (1-mask)*NEG
// grid (8 t-chunks, 64 b), block 256 (8 warps: warp computes one t per iter)
// ---------------------------------------------------------------------------
__global__ void k3a_scores(const float* __restrict__ emb,
                           const int* __restrict__ emask,
                           const float* __restrict__ ve) {
    int b = blockIdx.y;
    int t0 = blockIdx.x * 64;
    int tid = threadIdx.x;
    int warp = tid >> 5;
    int lane = tid & 31;
    __shared__ float s_ve[DD];
    for (int d = tid; d < DD; d += blockDim.x)
        s_ve[d] = ve[b * DD + d];
    __syncthreads();

#pragma unroll
    for (int i = 0; i < 8; i++) {
        int t = t0 + i * 8 + warp;
        const float* e = emb + ((size_t)(b * TT + t)) * DD;
        float acc = 0.0f;
#pragma unroll 4
        for (int d = lane; d < DD; d += 32)
            acc += e[d] * s_ve[d];
#pragma unroll
        for (int o = 16; o; o >>= 1)
            acc += __shfl_xor_sync(0xffffffffu, acc, o);
        if (lane == 0)
            g_scores[b * TT + t] =
                acc + (1.0f - (float)emask[b * TT + t]) * NEGC;
    }
}

// ---------------------------------------------------------------------------
// K3b: softmax over T=512 per b. grid 64, block 512.
// ---------------------------------------------------------------------------
__global__ void k3b_softmax(float* __restrict__ out_pp) {
    int b = blockIdx.x;
    int tid = threadIdx.x;
    int warp = tid >> 5;
    int lane = tid & 31;
    __shared__ float red[16];
    __shared__ float s_mx, s_sum;

    float v = g_scores[b * TT + tid];

    // block max
    float mx = v;
#pragma unroll
    for (int o = 16; o; o >>= 1)
        mx = fmaxf(mx, __shfl_xor_sync(0xffffffffu, mx, o));
    if (lane == 0) red[warp] = mx;
    __syncthreads();
    if (tid < 32) {
        float m = (tid < 16) ? red[tid] : -3.4e38f;
#pragma unroll
        for (int o = 8; o; o >>= 1)
            m = fmaxf(m, __shfl_xor_sync(0xffffffffu, m, o));
        if (tid == 0) s_mx = m;
    }
    __syncthreads();

    float ev = expf(v - s_mx);

    // block sum
    float s = ev;
#pragma unroll
    for (int o = 16; o; o >>= 1)
        s += __shfl_xor_sync(0xffffffffu, s, o);
    if (lane == 0) red[warp] = s;
    __syncthreads();
    if (tid < 32) {
        float m = (tid < 16) ? red[tid] : 0.0f;
#pragma unroll
        for (int o = 8; o; o >>= 1)
            m += __shfl_xor_sync(0xffffffffu, m, o);
        if (tid == 0) s_sum = m;
    }
    __syncthreads();

    out_pp[b * TT + tid] = ev / s_sum;
}

// ---------------------------------------------------------------------------
// K3c: pooled[b,d] = sum_t emb[b,t,d] * p[b,t]
// grid (8 t-chunks, 64 b), block 768 (one thread per d)
// ---------------------------------------------------------------------------
__global__ void k3c_pooled(const float* __restrict__ emb,
                           const float* __restrict__ pp,
                           float* __restrict__ out_pooled) {
    int b = blockIdx.y;
    int t0 = blockIdx.x * 64;
    int d = threadIdx.x;
    __shared__ float sp[64];
    if (threadIdx.x < 64)
        sp[threadIdx.x] = pp[b * TT + t0 + threadIdx.x];
    __syncthreads();

    const float* e = emb + ((size_t)(b * TT + t0)) * DD + d;
    float acc = 0.0f;
#pragma unroll 8
    for (int i = 0; i < 64; i++)
        acc += sp[i] * e[(size_t)i * DD];
    atomicAdd(&out_pooled[b * DD + d], acc);
}

// ---------------------------------------------------------------------------
extern "C" void kernel_launch(void* const* d_in, const int* in_sizes, int n_in,
                              void* d_out, int out_size) {
    const float* emb = (const float*)d_in[0];      // (B,T,D) f32
    const int* emask = (const int*)d_in[1];        // (B,T) i32
    const int* vmask = (const int*)d_in[2];        // (B,V) i32
    const float* W = (const float*)d_in[3];        // (V,D) f32

    float* out = (float*)d_out;
    float* out_ve = out;                            // (B,D)
    float* out_pooled = out + BB * DD;              // (B,D)
    float* out_vp = out + 2 * BB * DD;              // (B,V)
    float* out_pp = out + 2 * BB * DD + BB * VV;    // (B,T)

    k0_zero<<<(BB * DD + 255) / 256, 256>>>(out_pooled);
    k1_msum<<<dim3(8, BB), 768>>>(emb, emask);
    k2_value<<<BB, 640>>>(W, vmask, out_ve, out_vp);
    k3a_scores<<<dim3(8, BB), 256>>>(emb, emask, out_ve);
    k3b_softmax<<<BB, 512>>>(out_pp);
    k3c_pooled<<<dim3(8, BB), 768>>>(emb, out_pp, out_pooled);
}

// round 2
// speedup vs baseline: 1.3441x; 1.3441x over previous
#include <cuda_runtime.h>

#define BB 64
#define TT 512
#define DD 768
#define VV 20
#define NEGC (-1000000000.0f)
#define NCH 16            // t-chunks for partial-sum kernels (512/NCH = 32 t per chunk)
#define D4 (DD / 4)       // 192 float4 per row

// Scratch (no device allocation allowed)
__device__ float g_p1[NCH * BB * DD];   // k1 partials (masked sums)
__device__ float g_p2[NCH * BB * DD];   // k3c partials (pooled sums)
__device__ float g_scores[BB * TT];     // raw pooling scores

// ---------------------------------------------------------------------------
// K1: partial masked sums. grid (NCH, B), block 192 (one thread per float4 col)
// p1[c][b][d] = sum over 32 tokens of mask * emb
// ---------------------------------------------------------------------------
__global__ void k1_msum(const float4* __restrict__ emb,
                        const int* __restrict__ emask) {
    int b = blockIdx.y;
    int c = blockIdx.x;
    int t0 = c * (TT / NCH);
    int tid = threadIdx.x;
    __shared__ float sm[TT / NCH];
    if (tid < TT / NCH)
        sm[tid] = (float)emask[b * TT + t0 + tid];
    __syncthreads();

    const float4* e = emb + (size_t)(b * TT + t0) * D4 + tid;
    float4 acc = make_float4(0.f, 0.f, 0.f, 0.f);
#pragma unroll 8
    for (int i = 0; i < TT / NCH; i++) {
        float m = sm[i];
        float4 v = e[(size_t)i * D4];
        acc.x += m * v.x; acc.y += m * v.y;
        acc.z += m * v.z; acc.w += m * v.w;
    }
    ((float4*)g_p1)[(size_t)(c * BB + b) * D4 + tid] = acc;
}

// ---------------------------------------------------------------------------
// K2: reduce msum partials, value softmax over V=20, value_embedding.
// grid B, block 768 (24 warps; warps 0..19 do the V dots)
// ---------------------------------------------------------------------------
__global__ void k2_value(const float* __restrict__ W,
                         const int* __restrict__ vmask,
                         float* __restrict__ out_ve,
                         float* __restrict__ out_vp) {
    int b = blockIdx.x;
    int tid = threadIdx.x;
    int warp = tid >> 5;
    int lane = tid & 31;
    __shared__ float s_ms[DD];
    __shared__ float s_sc[VV];
    __shared__ float s_p[VV];

    // reduce NCH partials for this b
    {
        float acc = 0.f;
#pragma unroll
        for (int c = 0; c < NCH; c++)
            acc += g_p1[(size_t)(c * BB + b) * DD + tid];
        s_ms[tid] = acc;
    }
    __syncthreads();

    if (warp < VV) {
        const float* w = W + warp * DD;
        float acc = 0.f;
#pragma unroll
        for (int d = lane; d < DD; d += 32)
            acc += s_ms[d] * w[d];
#pragma unroll
        for (int o = 16; o; o >>= 1)
            acc += __shfl_xor_sync(0xffffffffu, acc, o);
        if (lane == 0)
            s_sc[warp] = acc + (1.0f - (float)vmask[b * VV + warp]) * NEGC;
    }
    __syncthreads();

    if (tid < 32) {
        float v = (tid < VV) ? s_sc[tid] : -3.4e38f;
        float mx = v;
#pragma unroll
        for (int o = 16; o; o >>= 1)
            mx = fmaxf(mx, __shfl_xor_sync(0xffffffffu, mx, o));
        float ev = (tid < VV) ? expf(v - mx) : 0.f;
        float s = ev;
#pragma unroll
        for (int o = 16; o; o >>= 1)
            s += __shfl_xor_sync(0xffffffffu, s, o);
        float p = ev / s;
        if (tid < VV) {
            s_p[tid] = p;
            out_vp[b * VV + tid] = p;
        }
    }
    __syncthreads();

    // value_embedding[b,d] = sum_v p[v] * W[v,d]
    float acc = 0.f;
#pragma unroll
    for (int v = 0; v < VV; v++)
        acc += s_p[v] * W[v * DD + tid];
    out_ve[b * DD + tid] = acc;
}

// ---------------------------------------------------------------------------
// K3a: pooling_scores[b,t] = <emb[b,t,:], ve[b,:]> + (1-mask)*NEG
// grid (T/8, B) = 4096 blocks, block 256 (8 warps, one token per warp)
// float4 loads: 6 independent LDG.128 per lane
// ---------------------------------------------------------------------------
__global__ void k3a_scores(const float4* __restrict__ emb,
                           const int* __restrict__ emask,
                           const float4* __restrict__ ve) {
    int b = blockIdx.y;
    int t = blockIdx.x * 8 + (threadIdx.x >> 5);
    int lane = threadIdx.x & 31;
    __shared__ float4 s_ve[D4];
    if (threadIdx.x < D4)
        s_ve[threadIdx.x] = ve[b * D4 + threadIdx.x];
    __syncthreads();

    const float4* e = emb + (size_t)(b * TT + t) * D4;
    float acc = 0.f;
#pragma unroll
    for (int k = 0; k < D4 / 32; k++) {
        float4 a = e[lane + k * 32];
        float4 w = s_ve[lane + k * 32];
        acc += a.x * w.x + a.y * w.y + a.z * w.z + a.w * w.w;
    }
#pragma unroll
    for (int o = 16; o; o >>= 1)
        acc += __shfl_xor_sync(0xffffffffu, acc, o);
    if (lane == 0)
        g_scores[b * TT + t] = acc + (1.0f - (float)emask[b * TT + t]) * NEGC;
}

// ---------------------------------------------------------------------------
// K3b: softmax over T=512 per b. grid B, block 512.
// ---------------------------------------------------------------------------
__global__ void k3b_softmax(float* __restrict__ out_pp) {
    int b = blockIdx.x;
    int tid = threadIdx.x;
    int warp = tid >> 5;
    int lane = tid & 31;
    __shared__ float red[16];
    __shared__ float s_mx, s_sum;

    float v = g_scores[b * TT + tid];

    float mx = v;
#pragma unroll
    for (int o = 16; o; o >>= 1)
        mx = fmaxf(mx, __shfl_xor_sync(0xffffffffu, mx, o));
    if (lane == 0) red[warp] = mx;
    __syncthreads();
    if (tid < 32) {
        float m = (tid < 16) ? red[tid] : -3.4e38f;
#pragma unroll
        for (int o = 8; o; o >>= 1)
            m = fmaxf(m, __shfl_xor_sync(0xffffffffu, m, o));
        if (tid == 0) s_mx = m;
    }
    __syncthreads();

    float ev = expf(v - s_mx);
    float s = ev;
#pragma unroll
    for (int o = 16; o; o >>= 1)
        s += __shfl_xor_sync(0xffffffffu, s, o);
    if (lane == 0) red[warp] = s;
    __syncthreads();
    if (tid < 32) {
        float m = (tid < 16) ? red[tid] : 0.f;
#pragma unroll
        for (int o = 8; o; o >>= 1)
            m += __shfl_xor_sync(0xffffffffu, m, o);
        if (tid == 0) s_sum = m;
    }
    __syncthreads();

    out_pp[b * TT + tid] = ev / s_sum;
}

// ---------------------------------------------------------------------------
// K3c: partial pooled sums. grid (NCH, B), block 192 (float4 per thread)
// p2[c][b][d] = sum over 32 tokens of pp * emb
// ---------------------------------------------------------------------------
__global__ void k3c_pooled(const float4* __restrict__ emb,
                           const float* __restrict__ pp) {
    int b = blockIdx.y;
    int c = blockIdx.x;
    int t0 = c * (TT / NCH);
    int tid = threadIdx.x;
    __shared__ float sp[TT / NCH];
    if (tid < TT / NCH)
        sp[tid] = pp[b * TT + t0 + tid];
    __syncthreads();

    const float4* e = emb + (size_t)(b * TT + t0) * D4 + tid;
    float4 acc = make_float4(0.f, 0.f, 0.f, 0.f);
#pragma unroll 8
    for (int i = 0; i < TT / NCH; i++) {
        float m = sp[i];
        float4 v = e[(size_t)i * D4];
        acc.x += m * v.x; acc.y += m * v.y;
        acc.z += m * v.z; acc.w += m * v.w;
    }
    ((float4*)g_p2)[(size_t)(c * BB + b) * D4 + tid] = acc;
}

// ---------------------------------------------------------------------------
// K4: reduce pooled partials -> out_pooled. 49152 elems.
// ---------------------------------------------------------------------------
__global__ void k4_reduce(float* __restrict__ out_pooled) {
    int i = blockIdx.x * blockDim.x + threadIdx.x;
    if (i < BB * DD) {
        float acc = 0.f;
#pragma unroll
        for (int c = 0; c < NCH; c++)
            acc += g_p2[(size_t)c * BB * DD + i];
        out_pooled[i] = acc;
    }
}

// ---------------------------------------------------------------------------
extern "C" void kernel_launch(void* const* d_in, const int* in_sizes, int n_in,
                              void* d_out, int out_size) {
    const float* emb = (const float*)d_in[0];      // (B,T,D) f32
    const int* emask = (const int*)d_in[1];        // (B,T) i32
    const int* vmask = (const int*)d_in[2];        // (B,V) i32
    const float* W = (const float*)d_in[3];        // (V,D) f32

    float* out = (float*)d_out;
    float* out_ve = out;                            // (B,D)
    float* out_pooled = out + BB * DD;              // (B,D)
    float* out_vp = out + 2 * BB * DD;              // (B,V)
    float* out_pp = out + 2 * BB * DD + BB * VV;    // (B,T)

    k1_msum<<<dim3(NCH, BB), 192>>>((const float4*)emb, emask);
    k2_value<<<BB, 768>>>(W, vmask, out_ve, out_vp);
    k3a_scores<<<dim3(TT / 8, BB), 256>>>((const float4*)emb, emask,
                                          (const float4*)out_ve);
    k3b_softmax<<<BB, 512>>>(out_pp);
    k3c_pooled<<<dim3(NCH, BB), 192>>>((const float4*)emb, out_pp);
    k4_reduce<<<(BB * DD + 255) / 256, 256>>>(out_pooled);
}

// round 3
// speedup vs baseline: 1.3966x; 1.0391x over previous
#include <cuda_runtime.h>

#define BB 64
#define TT 512
#define DD 768
#define VV 20
#define NEGC (-1000000000.0f)
#define NCH 16            // t-chunks for partial-sum kernels (512/NCH = 32 t per chunk)
#define TCH (TT / NCH)    // 32 tokens per chunk
#define D4 (DD / 4)       // 192 float4 per row

// Scratch (no device allocation allowed)
__device__ float g_p1[NCH * BB * DD];   // k1 partials (masked sums)
__device__ float g_p2[NCH * BB * DD];   // k3c partials (pooled sums)
__device__ float g_scores[BB * TT];     // raw pooling scores

// ---------------------------------------------------------------------------
// K1: partial masked sums. grid (NCH, B), block 192 (one thread per float4 col)
// ---------------------------------------------------------------------------
__global__ void k1_msum(const float4* __restrict__ emb,
                        const int* __restrict__ emask) {
    int b = blockIdx.y;
    int c = blockIdx.x;
    int t0 = c * TCH;
    int tid = threadIdx.x;
    __shared__ float sm[TCH];
    if (tid < TCH)
        sm[tid] = (float)emask[b * TT + t0 + tid];
    __syncthreads();

    const float4* e = emb + (size_t)(b * TT + t0) * D4 + tid;
    float4 acc = make_float4(0.f, 0.f, 0.f, 0.f);
#pragma unroll 8
    for (int i = 0; i < TCH; i++) {
        float m = sm[i];
        float4 v = e[(size_t)i * D4];
        acc.x += m * v.x; acc.y += m * v.y;
        acc.z += m * v.z; acc.w += m * v.w;
    }
    ((float4*)g_p1)[(size_t)(c * BB + b) * D4 + tid] = acc;
}

// ---------------------------------------------------------------------------
// K2: reduce msum partials, value softmax over V=20, value_embedding.
// grid B, block 768
// ---------------------------------------------------------------------------
__global__ void k2_value(const float* __restrict__ W,
                         const int* __restrict__ vmask,
                         float* __restrict__ out_ve,
                         float* __restrict__ out_vp) {
    int b = blockIdx.x;
    int tid = threadIdx.x;
    int warp = tid >> 5;
    int lane = tid & 31;
    __shared__ float s_ms[DD];
    __shared__ float s_sc[VV];
    __shared__ float s_p[VV];

    {
        float acc = 0.f;
#pragma unroll
        for (int c = 0; c < NCH; c++)
            acc += g_p1[(size_t)(c * BB + b) * DD + tid];
        s_ms[tid] = acc;
    }
    __syncthreads();

    if (warp < VV) {
        const float* w = W + warp * DD;
        float acc = 0.f;
#pragma unroll
        for (int d = lane; d < DD; d += 32)
            acc += s_ms[d] * w[d];
#pragma unroll
        for (int o = 16; o; o >>= 1)
            acc += __shfl_xor_sync(0xffffffffu, acc, o);
        if (lane == 0)
            s_sc[warp] = acc + (1.0f - (float)vmask[b * VV + warp]) * NEGC;
    }
    __syncthreads();

    if (tid < 32) {
        float v = (tid < VV) ? s_sc[tid] : -3.4e38f;
        float mx = v;
#pragma unroll
        for (int o = 16; o; o >>= 1)
            mx = fmaxf(mx, __shfl_xor_sync(0xffffffffu, mx, o));
        float ev = (tid < VV) ? expf(v - mx) : 0.f;
        float s = ev;
#pragma unroll
        for (int o = 16; o; o >>= 1)
            s += __shfl_xor_sync(0xffffffffu, s, o);
        float p = ev / s;
        if (tid < VV) {
            s_p[tid] = p;
            out_vp[b * VV + tid] = p;
        }
    }
    __syncthreads();

    float acc = 0.f;
#pragma unroll
    for (int v = 0; v < VV; v++)
        acc += s_p[v] * W[v * DD + tid];
    out_ve[b * DD + tid] = acc;
}

// ---------------------------------------------------------------------------
// K3a: pooling_scores[b,t] = <emb[b,t,:], ve[b,:]> + (1-mask)*NEG
// grid (T/8, B), block 256 (warp per token), float4 loads
// ---------------------------------------------------------------------------
__global__ void k3a_scores(const float4* __restrict__ emb,
                           const int* __restrict__ emask,
                           const float4* __restrict__ ve) {
    int b = blockIdx.y;
    int t = blockIdx.x * 8 + (threadIdx.x >> 5);
    int lane = threadIdx.x & 31;
    __shared__ float4 s_ve[D4];
    if (threadIdx.x < D4)
        s_ve[threadIdx.x] = ve[b * D4 + threadIdx.x];
    __syncthreads();

    const float4* e = emb + (size_t)(b * TT + t) * D4;
    float acc = 0.f;
#pragma unroll
    for (int k = 0; k < D4 / 32; k++) {
        float4 a = e[lane + k * 32];
        float4 w = s_ve[lane + k * 32];
        acc += a.x * w.x + a.y * w.y + a.z * w.z + a.w * w.w;
    }
#pragma unroll
    for (int o = 16; o; o >>= 1)
        acc += __shfl_xor_sync(0xffffffffu, acc, o);
    if (lane == 0)
        g_scores[b * TT + t] = acc + (1.0f - (float)emask[b * TT + t]) * NEGC;
}

// ---------------------------------------------------------------------------
// K3c (fused softmax + pooled partials). grid (NCH, B), block 192.
// Each block: recompute softmax normalization over the 512 scores of b
// (2 KB from L2, block reduce), derive probs for its 32-token chunk,
// write out_pp chunk, then accumulate partial pooled sums.
// ---------------------------------------------------------------------------
__global__ void k3c_fused(const float4* __restrict__ emb,
                          float* __restrict__ out_pp) {
    int b = blockIdx.y;
    int c = blockIdx.x;
    int t0 = c * TCH;
    int tid = threadIdx.x;
    int warp = tid >> 5;
    int lane = tid & 31;

    __shared__ float red[6];
    __shared__ float s_mx, s_sum;
    __shared__ float sp[TCH];

    // --- local (register) view of all 512 scores: 512/192 -> up to 3 each
    float v0 = -3.4e38f, v1 = -3.4e38f, v2 = 0.f;
    const float* sc = g_scores + b * TT;
    v0 = sc[tid];
    v1 = sc[tid + 192];
    if (tid < TT - 384) v2 = sc[tid + 384]; else v2 = -3.4e38f;

    // block max
    float mx = fmaxf(v0, fmaxf(v1, v2));
#pragma unroll
    for (int o = 16; o; o >>= 1)
        mx = fmaxf(mx, __shfl_xor_sync(0xffffffffu, mx, o));
    if (lane == 0) red[warp] = mx;
    __syncthreads();
    if (tid == 0) {
        float m = red[0];
#pragma unroll
        for (int i = 1; i < 6; i++) m = fmaxf(m, red[i]);
        s_mx = m;
    }
    __syncthreads();
    float gm = s_mx;

    // block sum of exp
    float s = expf(v0 - gm) + expf(v1 - gm) +
              ((tid < TT - 384) ? expf(v2 - gm) : 0.f);
#pragma unroll
    for (int o = 16; o; o >>= 1)
        s += __shfl_xor_sync(0xffffffffu, s, o);
    if (lane == 0) red[warp] = s;
    __syncthreads();
    if (tid == 0) {
        float m = red[0];
#pragma unroll
        for (int i = 1; i < 6; i++) m += red[i];
        s_sum = m;
    }
    __syncthreads();
    float inv = 1.0f / s_sum;

    // probs for this block's 32-token chunk; block 0..NCH-1 writes its slice
    if (tid < TCH) {
        float p = expf(sc[t0 + tid] - gm) * inv;
        sp[tid] = p;
        out_pp[b * TT + t0 + tid] = p;
    }
    __syncthreads();

    // partial pooled sums over the chunk
    const float4* e = emb + (size_t)(b * TT + t0) * D4 + tid;
    float4 acc = make_float4(0.f, 0.f, 0.f, 0.f);
#pragma unroll 8
    for (int i = 0; i < TCH; i++) {
        float m = sp[i];
        float4 v = e[(size_t)i * D4];
        acc.x += m * v.x; acc.y += m * v.y;
        acc.z += m * v.z; acc.w += m * v.w;
    }
    ((float4*)g_p2)[(size_t)(c * BB + b) * D4 + tid] = acc;
}

// ---------------------------------------------------------------------------
// K4: reduce pooled partials -> out_pooled.
// ---------------------------------------------------------------------------
__global__ void k4_reduce(float* __restrict__ out_pooled) {
    int i = blockIdx.x * blockDim.x + threadIdx.x;
    if (i < BB * DD) {
        float acc = 0.f;
#pragma unroll
        for (int c = 0; c < NCH; c++)
            acc += g_p2[(size_t)c * BB * DD + i];
        out_pooled[i] = acc;
    }
}

// ---------------------------------------------------------------------------
extern "C" void kernel_launch(void* const* d_in, const int* in_sizes, int n_in,
                              void* d_out, int out_size) {
    const float* emb = (const float*)d_in[0];      // (B,T,D) f32
    const int* emask = (const int*)d_in[1];        // (B,T) i32
    const int* vmask = (const int*)d_in[2];        // (B,V) i32
    const float* W = (const float*)d_in[3];        // (V,D) f32

    float* out = (float*)d_out;
    float* out_ve = out;                            // (B,D)
    float* out_pooled = out + BB * DD;              // (B,D)
    float* out_vp = out + 2 * BB * DD;              // (B,V)
    float* out_pp = out + 2 * BB * DD + BB * VV;    // (B,T)

    k1_msum<<<dim3(NCH, BB), 192>>>((const float4*)emb, emask);
    k2_value<<<BB, 768>>>(W, vmask, out_ve, out_vp);
    k3a_scores<<<dim3(TT / 8, BB), 256>>>((const float4*)emb, emask,
                                          (const float4*)out_ve);
    k3c_fused<<<dim3(NCH, BB), 192>>>((const float4*)emb, out_pp);
    k4_reduce<<<(BB * DD + 255) / 256, 256>>>(out_pooled);
}

// round 4
// speedup vs baseline: 1.6142x; 1.1558x over previous
#include <cuda_runtime.h>

#define BB 64
#define TT 512
#define DD 768
#define VV 20
#define NEGC (-1000000000.0f)
#define NCH 16            // t-chunks for partial-sum kernels
#define TCH (TT / NCH)    // 32 tokens per chunk
#define D4 (DD / 4)       // 192 float4 per row

// Scratch (no device allocation allowed)
__device__ __align__(16) float g_p1[NCH * BB * DD];   // k1 partials (masked sums)
__device__ float g_scores[BB * TT];                   // raw pooling scores

// ---------------------------------------------------------------------------
// K1: partial masked sums. grid (NCH, B), block 192 (one thread per float4 col)
// Explicit 8-deep load staging to force MLP=8.
// ---------------------------------------------------------------------------
__global__ __launch_bounds__(192) void k1_msum(const float4* __restrict__ emb,
                                               const int* __restrict__ emask) {
    int b = blockIdx.y;
    int c = blockIdx.x;
    int t0 = c * TCH;
    int tid = threadIdx.x;
    __shared__ float sm[TCH];
    if (tid < TCH)
        sm[tid] = (float)emask[b * TT + t0 + tid];
    __syncthreads();

    const float4* e = emb + (size_t)(b * TT + t0) * D4 + tid;
    float4 acc = make_float4(0.f, 0.f, 0.f, 0.f);
    float4 r[8];
#pragma unroll
    for (int i = 0; i < 8; i++) r[i] = e[(size_t)i * D4];

#pragma unroll
    for (int base = 0; base < TCH; base += 8) {
        float4 n[8];
        if (base + 8 < TCH) {
#pragma unroll
            for (int i = 0; i < 8; i++)
                n[i] = e[(size_t)(base + 8 + i) * D4];
        }
#pragma unroll
        for (int i = 0; i < 8; i++) {
            float m = sm[base + i];
            acc.x = fmaf(m, r[i].x, acc.x);
            acc.y = fmaf(m, r[i].y, acc.y);
            acc.z = fmaf(m, r[i].z, acc.z);
            acc.w = fmaf(m, r[i].w, acc.w);
        }
        if (base + 8 < TCH) {
#pragma unroll
            for (int i = 0; i < 8; i++) r[i] = n[i];
        }
    }
    ((float4*)g_p1)[(size_t)(c * BB + b) * D4 + tid] = acc;
}

// ---------------------------------------------------------------------------
// K2: reduce msum partials, value softmax over V=20, value_embedding.
// Also zero-inits out_pooled (grid covers exactly B x D) for k3c's atomics.
// grid B, block 768
// ---------------------------------------------------------------------------
__global__ void k2_value(const float* __restrict__ W,
                         const int* __restrict__ vmask,
                         float* __restrict__ out_ve,
                         float* __restrict__ out_vp,
                         float* __restrict__ out_pooled) {
    int b = blockIdx.x;
    int tid = threadIdx.x;
    int warp = tid >> 5;
    int lane = tid & 31;
    __shared__ float s_ms[DD];
    __shared__ float s_sc[VV];
    __shared__ float s_p[VV];

    out_pooled[b * DD + tid] = 0.f;

    {
        float acc = 0.f;
#pragma unroll
        for (int c = 0; c < NCH; c++)
            acc += g_p1[(size_t)(c * BB + b) * DD + tid];
        s_ms[tid] = acc;
    }
    __syncthreads();

    if (warp < VV) {
        const float* w = W + warp * DD;
        float acc = 0.f;
#pragma unroll
        for (int d = lane; d < DD; d += 32)
            acc += s_ms[d] * w[d];
#pragma unroll
        for (int o = 16; o; o >>= 1)
            acc += __shfl_xor_sync(0xffffffffu, acc, o);
        if (lane == 0)
            s_sc[warp] = acc + (1.0f - (float)vmask[b * VV + warp]) * NEGC;
    }
    __syncthreads();

    if (tid < 32) {
        float v = (tid < VV) ? s_sc[tid] : -3.4e38f;
        float mx = v;
#pragma unroll
        for (int o = 16; o; o >>= 1)
            mx = fmaxf(mx, __shfl_xor_sync(0xffffffffu, mx, o));
        float ev = (tid < VV) ? expf(v - mx) : 0.f;
        float s = ev;
#pragma unroll
        for (int o = 16; o; o >>= 1)
            s += __shfl_xor_sync(0xffffffffu, s, o);
        float p = ev / s;
        if (tid < VV) {
            s_p[tid] = p;
            out_vp[b * VV + tid] = p;
        }
    }
    __syncthreads();

    float acc = 0.f;
#pragma unroll
    for (int v = 0; v < VV; v++)
        acc += s_p[v] * W[v * DD + tid];
    out_ve[b * DD + tid] = acc;
}

// ---------------------------------------------------------------------------
// K3a: pooling_scores[b,t] = <emb[b,t,:], ve[b,:]> + (1-mask)*NEG
// grid (T/8, B), block 256 (warp per token), float4 loads
// ---------------------------------------------------------------------------
__global__ void k3a_scores(const float4* __restrict__ emb,
                           const int* __restrict__ emask,
                           const float4* __restrict__ ve) {
    int b = blockIdx.y;
    int t = blockIdx.x * 8 + (threadIdx.x >> 5);
    int lane = threadIdx.x & 31;
    __shared__ float4 s_ve[D4];
    if (threadIdx.x < D4)
        s_ve[threadIdx.x] = ve[b * D4 + threadIdx.x];
    __syncthreads();

    const float4* e = emb + (size_t)(b * TT + t) * D4;
    float4 a0 = e[lane];
    float4 a1 = e[lane + 32];
    float4 a2 = e[lane + 64];
    float4 a3 = e[lane + 96];
    float4 a4 = e[lane + 128];
    float4 a5 = e[lane + 160];
    float acc = 0.f;
    {
        float4 w = s_ve[lane];
        acc += a0.x * w.x + a0.y * w.y + a0.z * w.z + a0.w * w.w;
        w = s_ve[lane + 32];
        acc += a1.x * w.x + a1.y * w.y + a1.z * w.z + a1.w * w.w;
        w = s_ve[lane + 64];
        acc += a2.x * w.x + a2.y * w.y + a2.z * w.z + a2.w * w.w;
        w = s_ve[lane + 96];
        acc += a3.x * w.x + a3.y * w.y + a3.z * w.z + a3.w * w.w;
        w = s_ve[lane + 128];
        acc += a4.x * w.x + a4.y * w.y + a4.z * w.z + a4.w * w.w;
        w = s_ve[lane + 160];
        acc += a5.x * w.x + a5.y * w.y + a5.z * w.z + a5.w * w.w;
    }
#pragma unroll
    for (int o = 16; o; o >>= 1)
        acc += __shfl_xor_sync(0xffffffffu, acc, o);
    if (lane == 0)
        g_scores[b * TT + t] = acc + (1.0f - (float)emask[b * TT + t]) * NEGC;
}

// ---------------------------------------------------------------------------
// K3c (fused softmax + pooled accumulation). grid (NCH, B), block 192.
// Recomputes softmax stats per block (2 KB L2), writes out_pp chunk,
// streams its 32-token chunk with 8-deep staging, atomics into out_pooled.
// ---------------------------------------------------------------------------
__global__ __launch_bounds__(192) void k3c_fused(const float4* __restrict__ emb,
                                                 float* __restrict__ out_pp,
                                                 float* __restrict__ out_pooled) {
    int b = blockIdx.y;
    int c = blockIdx.x;
    int t0 = c * TCH;
    int tid = threadIdx.x;
    int warp = tid >> 5;
    int lane = tid & 31;

    __shared__ float red[6];
    __shared__ float s_mx, s_sum;
    __shared__ float sp[TCH];

    const float* sc = g_scores + b * TT;
    float v0 = sc[tid];
    float v1 = sc[tid + 192];
    float v2 = (tid < TT - 384) ? sc[tid + 384] : -3.4e38f;

    // block max
    float mx = fmaxf(v0, fmaxf(v1, v2));
#pragma unroll
    for (int o = 16; o; o >>= 1)
        mx = fmaxf(mx, __shfl_xor_sync(0xffffffffu, mx, o));
    if (lane == 0) red[warp] = mx;
    __syncthreads();
    if (tid == 0) {
        float m = red[0];
#pragma unroll
        for (int i = 1; i < 6; i++) m = fmaxf(m, red[i]);
        s_mx = m;
    }
    __syncthreads();
    float gm = s_mx;

    // block sum of exp
    float s = expf(v0 - gm) + expf(v1 - gm) +
              ((tid < TT - 384) ? expf(v2 - gm) : 0.f);
#pragma unroll
    for (int o = 16; o; o >>= 1)
        s += __shfl_xor_sync(0xffffffffu, s, o);
    if (lane == 0) red[warp] = s;
    __syncthreads();
    if (tid == 0) {
        float m = red[0];
#pragma unroll
        for (int i = 1; i < 6; i++) m += red[i];
        s_sum = m;
    }
    __syncthreads();
    float inv = 1.0f / s_sum;

    if (tid < TCH) {
        float p = expf(sc[t0 + tid] - gm) * inv;
        sp[tid] = p;
        out_pp[b * TT + t0 + tid] = p;
    }
    __syncthreads();

    // streamed pooled partial with 8-deep staging
    const float4* e = emb + (size_t)(b * TT + t0) * D4 + tid;
    float4 acc = make_float4(0.f, 0.f, 0.f, 0.f);
    float4 r[8];
#pragma unroll
    for (int i = 0; i < 8; i++) r[i] = e[(size_t)i * D4];

#pragma unroll
    for (int base = 0; base < TCH; base += 8) {
        float4 n[8];
        if (base + 8 < TCH) {
#pragma unroll
            for (int i = 0; i < 8; i++)
                n[i] = e[(size_t)(base + 8 + i) * D4];
        }
#pragma unroll
        for (int i = 0; i < 8; i++) {
            float m = sp[base + i];
            acc.x = fmaf(m, r[i].x, acc.x);
            acc.y = fmaf(m, r[i].y, acc.y);
            acc.z = fmaf(m, r[i].z, acc.z);
            acc.w = fmaf(m, r[i].w, acc.w);
        }
        if (base + 8 < TCH) {
#pragma unroll
            for (int i = 0; i < 8; i++) r[i] = n[i];
        }
    }

    float* op = out_pooled + b * DD + tid * 4;
    atomicAdd(op + 0, acc.x);
    atomicAdd(op + 1, acc.y);
    atomicAdd(op + 2, acc.z);
    atomicAdd(op + 3, acc.w);
}

// ---------------------------------------------------------------------------
extern "C" void kernel_launch(void* const* d_in, const int* in_sizes, int n_in,
                              void* d_out, int out_size) {
    const float* emb = (const float*)d_in[0];      // (B,T,D) f32
    const int* emask = (const int*)d_in[1];        // (B,T) i32
    const int* vmask = (const int*)d_in[2];        // (B,V) i32
    const float* W = (const float*)d_in[3];        // (V,D) f32

    float* out = (float*)d_out;
    float* out_ve = out;                            // (B,D)
    float* out_pooled = out + BB * DD;              // (B,D)
    float* out_vp = out + 2 * BB * DD;              // (B,V)
    float* out_pp = out + 2 * BB * DD + BB * VV;    // (B,T)

    k1_msum<<<dim3(NCH, BB), 192>>>((const float4*)emb, emask);
    k2_value<<<BB, 768>>>(W, vmask, out_ve, out_vp, out_pooled);
    k3a_scores<<<dim3(TT / 8, BB), 256>>>((const float4*)emb, emask,
                                          (const float4*)out_ve);
    k3c_fused<<<dim3(NCH, BB), 192>>>((const float4*)emb, out_pp, out_pooled);
}